// round 13
// baseline (speedup 1.0000x reference)
#include <cuda_runtime.h>
#include <cstdint>

#define S_LEN 128
#define B_SZ  32
#define H_DIM 512
#define V_SZ  10000

typedef unsigned long long u64;

// ---------------- scratch (device globals; no allocation allowed) ----------------
__device__ float g_X[S_LEN * B_SZ * H_DIM];       // layer input / tops (8 MB)
__device__ float g_A[S_LEN * B_SZ * 3 * H_DIM];   // ax scratch / rounded Wy (24 MB)
__device__ float g_h0[B_SZ * H_DIM];              // layer-0 h
__device__ float g_h1[B_SZ * H_DIM];              // layer-1 h
__device__ float g_rh0[B_SZ * H_DIM];             // layer-0 r*h
__device__ float g_rh1[B_SZ * H_DIM];             // layer-1 r*h
__device__ int   g_is64;

// ---------------- hierarchical grid barrier (2 domains x 64 CTAs) ----------------
// Arrival: 8 groups x 8 CTAs on distinct 128-B lines (parallel), then 8 top
// arrivals. Release: flat volatile gen flip (proven R8/R11 pattern).
__device__ unsigned          g_cnt2[2 * 8 * 32];
__device__ unsigned          g_top2[2 * 32];
__device__ volatile unsigned g_gen2[2 * 32];

__device__ __forceinline__ void bg_barrier(int bg, int grp) {
    __syncthreads();
    if (threadIdx.x == 0) {
        volatile unsigned* genp = &g_gen2[bg * 32];
        unsigned gen = *genp;
        __threadfence();
        unsigned* cntp = &g_cnt2[(bg * 8 + grp) * 32];
        if (atomicAdd(cntp, 1u) == 7u) {
            atomicExch(cntp, 0u);          // reset before top-arrive; next-round
            __threadfence();               // arrivals gated by gen flip
            if (atomicAdd(&g_top2[bg * 32], 1u) == 7u) {
                atomicExch(&g_top2[bg * 32], 0u);
                __threadfence();
                *genp = gen + 1;
            }
        }
        unsigned it = 0;
        while (*genp == gen) {
            if (++it > 65536u) { __nanosleep(32); }
            if (it > 400000u) break;       // safety valve: never hang
        }
        __threadfence();
    }
    __syncthreads();
}

// ---------------- token dtype detector ----------------
__global__ void detect_kernel(const int* __restrict__ t32) {
    if (threadIdx.x == 0 && blockIdx.x == 0) {
        unsigned o = 0;
        for (int i = 0; i < 128; i++) o |= (unsigned)t32[2 * i + 1];
        g_is64 = (o == 0) ? 1 : 0;
    }
}

// ---------------- embedding gather (dtype-robust, clamped) ----------------
__global__ void embed_kernel(const void* __restrict__ tok,
                             const float* __restrict__ emb,
                             float* __restrict__ X) {
    int row = blockIdx.x;
    long long t;
    if (g_is64) t = ((const long long*)tok)[row];
    else        t = (long long)((const int*)tok)[row];
    if (t < 0) t = 0;
    if (t >= V_SZ) t = V_SZ - 1;
    const float4* src = (const float4*)(emb + (size_t)t * H_DIM);
    float4* dst = (float4*)(X + (size_t)row * H_DIM);
    for (int i = threadIdx.x; i < H_DIM / 4; i += blockDim.x) dst[i] = src[i];
}

// ---------------- tf32 mma + cp.async helpers ----------------
#define BM 128
#define BN 128
#define BKK 16
#define AST 20
#define BST_KN 136
#define BST_NK 20

__device__ __forceinline__ unsigned f2tf(float x) {
    unsigned r; asm("cvt.rna.tf32.f32 %0, %1;" : "=r"(r) : "f"(x)); return r;
}
__device__ __forceinline__ void mma8(float* c, const unsigned* a, const unsigned* b) {
    asm volatile(
        "mma.sync.aligned.m16n8k8.row.col.f32.tf32.tf32.f32 "
        "{%0,%1,%2,%3}, {%4,%5,%6,%7}, {%8,%9}, {%0,%1,%2,%3};\n"
        : "+f"(c[0]), "+f"(c[1]), "+f"(c[2]), "+f"(c[3])
        : "r"(a[0]), "r"(a[1]), "r"(a[2]), "r"(a[3]), "r"(b[0]), "r"(b[1]));
}
__device__ __forceinline__ void cpa16(unsigned dst, const void* src, bool pred) {
    int sz = pred ? 16 : 0;
    asm volatile("cp.async.cg.shared.global [%0], [%1], 16, %2;\n"
                 :: "r"(dst), "l"(src), "r"(sz));
}
__device__ __forceinline__ void cpa_commit() {
    asm volatile("cp.async.commit_group;\n" ::: "memory");
}
__device__ __forceinline__ void cpa_wait1() {
    asm volatile("cp.async.wait_group 1;\n" ::: "memory");
}
__device__ __forceinline__ unsigned smem_u32(const void* p) {
    return (unsigned)__cvta_generic_to_shared(p);
}
__device__ __forceinline__ void fma2(u64& acc, u64 a, u64 b) {
    asm("fma.rn.f32x2 %0, %1, %2, %0;" : "+l"(acc) : "l"(a), "l"(b));
}
__device__ __forceinline__ float acc_sum(u64 a) {
    unsigned lo, hi;
    asm("mov.b64 {%0,%1}, %2;" : "=r"(lo), "=r"(hi) : "l"(a));
    return __uint_as_float(lo) + __uint_as_float(hi);
}

// ---------------- tf32 pre-rounding kernel (tops in-place, Wy -> Wyr) -----------
#define TOPS_N4 (S_LEN * B_SZ * H_DIM / 4)   // 524288
#define WY_N4   (V_SZ * H_DIM / 4)           // 1280000
__global__ void round_tf32_kernel(float4* __restrict__ X,
                                  const float4* __restrict__ Wy,
                                  float4* __restrict__ Wyr) {
    int stride = gridDim.x * blockDim.x;
    int start = blockIdx.x * blockDim.x + threadIdx.x;
    for (int i = start; i < WY_N4; i += stride) {
        float4 v = Wy[i];
        v.x = __uint_as_float(f2tf(v.x)); v.y = __uint_as_float(f2tf(v.y));
        v.z = __uint_as_float(f2tf(v.z)); v.w = __uint_as_float(f2tf(v.w));
        Wyr[i] = v;
    }
    for (int i = start; i < TOPS_N4; i += stride) {
        float4 v = X[i];
        v.x = __uint_as_float(f2tf(v.x)); v.y = __uint_as_float(f2tf(v.y));
        v.z = __uint_as_float(f2tf(v.z)); v.w = __uint_as_float(f2tf(v.w));
        X[i] = v;
    }
}

// ---------- fused 3-gate input GEMM for layer 0 (2-stage cp.async) --------------
__global__ __launch_bounds__(256, 2)
void gemm_ax(const float* __restrict__ A,          // X [M,512]
             const float* __restrict__ Wxl,        // [3,512,512]
             const float* __restrict__ bxl,        // [3,512]
             float* __restrict__ C) {              // [M,1536]
    __shared__ float As[2][BM * AST];
    __shared__ float Bs[2][BKK * BST_KN];

    int tid = threadIdx.x;
    int lane = tid & 31, warp = tid >> 5;
    int wr = warp >> 2, wc = warp & 3;
    int m0 = blockIdx.y * BM, n0 = blockIdx.x * BN;
    int g = n0 >> 9, col0 = n0 & 511;
    const float* Bg = Wxl + (size_t)g * H_DIM * H_DIM;

    const int ra = tid >> 1, ha = tid & 1;
    const int krb = tid >> 4, csb = tid & 15;
    const float* Asrc = A + (size_t)(m0 + ra) * H_DIM + ha * 8;
    const float* Bsrc = Bg + (size_t)krb * H_DIM + col0 + csb * 8;

    float c[4][4][4];
    #pragma unroll
    for (int i = 0; i < 4; i++)
        #pragma unroll
        for (int j = 0; j < 4; j++)
            #pragma unroll
            for (int k = 0; k < 4; k++) c[i][j][k] = 0.f;

    const int NK = H_DIM / BKK;
    {
        unsigned da0 = smem_u32(&As[0][ra * AST + ha * 8]);
        cpa16(da0, Asrc, true); cpa16(da0 + 16, Asrc + 4, true);
        unsigned db0 = smem_u32(&Bs[0][krb * BST_KN + csb * 8]);
        cpa16(db0, Bsrc, true); cpa16(db0 + 16, Bsrc + 4, true);
        cpa_commit();
    }

    for (int it = 0; it < NK; it++) {
        if (it + 1 < NK) {
            int kk = (it + 1) * BKK, buf = (it + 1) & 1;
            unsigned da = smem_u32(&As[buf][ra * AST + ha * 8]);
            cpa16(da, Asrc + kk, true); cpa16(da + 16, Asrc + kk + 4, true);
            unsigned db = smem_u32(&Bs[buf][krb * BST_KN + csb * 8]);
            cpa16(db, Bsrc + (size_t)kk * H_DIM, true);
            cpa16(db + 16, Bsrc + (size_t)kk * H_DIM + 4, true);
        }
        cpa_commit();
        cpa_wait1();
        __syncthreads();

        const float* Ab = As[it & 1];
        const float* Bb = Bs[it & 1];
        int ar = lane >> 2, ak = lane & 3;
        #pragma unroll
        for (int kq = 0; kq < BKK; kq += 8) {
            unsigned af[4][4], bf[4][2];
            #pragma unroll
            for (int mt = 0; mt < 4; mt++) {
                int rb = wr * 64 + mt * 16;
                af[mt][0] = f2tf(Ab[(rb + ar)     * AST + kq + ak]);
                af[mt][1] = f2tf(Ab[(rb + ar + 8) * AST + kq + ak]);
                af[mt][2] = f2tf(Ab[(rb + ar)     * AST + kq + ak + 4]);
                af[mt][3] = f2tf(Ab[(rb + ar + 8) * AST + kq + ak + 4]);
            }
            #pragma unroll
            for (int nt = 0; nt < 4; nt++) {
                int cb = wc * 32 + nt * 8 + (lane >> 2);
                bf[nt][0] = f2tf(Bb[(kq + ak)     * BST_KN + cb]);
                bf[nt][1] = f2tf(Bb[(kq + ak + 4) * BST_KN + cb]);
            }
            #pragma unroll
            for (int mt = 0; mt < 4; mt++)
                #pragma unroll
                for (int nt = 0; nt < 4; nt++)
                    mma8(c[mt][nt], af[mt], bf[nt]);
        }
        __syncthreads();
    }

    #pragma unroll
    for (int mt = 0; mt < 4; mt++) {
        #pragma unroll
        for (int nt = 0; nt < 4; nt++) {
            int r0 = m0 + wr * 64 + mt * 16 + (lane >> 2);
            int cc = n0 + wc * 32 + nt * 8 + (lane & 3) * 2;
            float bv0 = bxl[g * H_DIM + (cc & 511)];
            float bv1 = bxl[g * H_DIM + ((cc + 1) & 511)];
            C[(size_t)r0 * 1536 + cc]           = c[mt][nt][0] + bv0;
            C[(size_t)r0 * 1536 + cc + 1]       = c[mt][nt][1] + bv1;
            C[(size_t)(r0 + 8) * 1536 + cc]     = c[mt][nt][2] + bv0;
            C[(size_t)(r0 + 8) * 1536 + cc + 1] = c[mt][nt][3] + bv1;
        }
    }
}

// ------- logits GEMM, 3-stage cp.async; operands PRE-ROUNDED to tf32 -----------
#define GBUF 2560
__global__ __launch_bounds__(256, 2)
void gemm_bt(const float* __restrict__ A,
             const float* __restrict__ Bm,
             const float* __restrict__ bias,
             float* __restrict__ C, int N) {
    extern __shared__ float sm[];
    float* AsB = sm;
    float* BsB = sm + 3 * GBUF;

    int tid = threadIdx.x;
    int lane = tid & 31, warp = tid >> 5;
    int wr = warp >> 2, wc = warp & 3;
    int m0 = blockIdx.y * BM, n0 = blockIdx.x * BN;

    const int ra = tid >> 1, ha = tid & 1;
    const int gn = n0 + ra;
    const bool bok = (gn < N);
    const float* Asrc = A + (size_t)(m0 + ra) * H_DIM + ha * 8;
    const float* Bsrc = Bm + (size_t)(bok ? gn : 0) * H_DIM + ha * 8;

    float c[4][4][4];
    #pragma unroll
    for (int i = 0; i < 4; i++)
        #pragma unroll
        for (int j = 0; j < 4; j++)
            #pragma unroll
            for (int k = 0; k < 4; k++) c[i][j][k] = 0.f;

    const int NK = H_DIM / BKK;
    #pragma unroll
    for (int s = 0; s < 2; s++) {
        int kk = s * BKK;
        unsigned da = smem_u32(&AsB[s * GBUF + ra * AST + ha * 8]);
        cpa16(da, Asrc + kk, true); cpa16(da + 16, Asrc + kk + 4, true);
        unsigned db = smem_u32(&BsB[s * GBUF + ra * BST_NK + ha * 8]);
        cpa16(db, Bsrc + kk, bok); cpa16(db + 16, Bsrc + kk + 4, bok);
        cpa_commit();
    }

    int buf = 0;
    for (int it = 0; it < NK; it++) {
        cpa_wait1();
        __syncthreads();

        const float* Ab = &AsB[buf * GBUF];
        const float* Bb = &BsB[buf * GBUF];
        int ar = lane >> 2, ak = lane & 3;
        #pragma unroll
        for (int kq = 0; kq < BKK; kq += 8) {
            unsigned af[4][4], bf[4][2];
            #pragma unroll
            for (int mt = 0; mt < 4; mt++) {
                int rb = wr * 64 + mt * 16;
                af[mt][0] = __float_as_uint(Ab[(rb + ar)     * AST + kq + ak]);
                af[mt][1] = __float_as_uint(Ab[(rb + ar + 8) * AST + kq + ak]);
                af[mt][2] = __float_as_uint(Ab[(rb + ar)     * AST + kq + ak + 4]);
                af[mt][3] = __float_as_uint(Ab[(rb + ar + 8) * AST + kq + ak + 4]);
            }
            #pragma unroll
            for (int nt = 0; nt < 4; nt++) {
                int cb = wc * 32 + nt * 8 + (lane >> 2);
                bf[nt][0] = __float_as_uint(Bb[cb * BST_NK + kq + ak]);
                bf[nt][1] = __float_as_uint(Bb[cb * BST_NK + kq + ak + 4]);
            }
            #pragma unroll
            for (int mt = 0; mt < 4; mt++)
                #pragma unroll
                for (int nt = 0; nt < 4; nt++)
                    mma8(c[mt][nt], af[mt], bf[nt]);
        }
        __syncthreads();

        if (it + 2 < NK) {
            int kk = (it + 2) * BKK;
            int nb = (it + 2) % 3;
            unsigned da = smem_u32(&AsB[nb * GBUF + ra * AST + ha * 8]);
            cpa16(da, Asrc + kk, true); cpa16(da + 16, Asrc + kk + 4, true);
            unsigned db = smem_u32(&BsB[nb * GBUF + ra * BST_NK + ha * 8]);
            cpa16(db, Bsrc + kk, bok); cpa16(db + 16, Bsrc + kk + 4, bok);
        }
        cpa_commit();
        buf = (buf + 1) % 3;
    }

    #pragma unroll
    for (int mt = 0; mt < 4; mt++) {
        #pragma unroll
        for (int nt = 0; nt < 4; nt++) {
            int r0 = m0 + wr * 64 + mt * 16 + (lane >> 2);
            int cc = n0 + wc * 32 + nt * 8 + (lane & 3) * 2;
            if (cc < N) {
                float bv = bias[cc];
                C[(size_t)r0 * N + cc]       = c[mt][nt][0] + bv;
                C[(size_t)(r0 + 8) * N + cc] = c[mt][nt][2] + bv;
            }
            if (cc + 1 < N) {
                float bv = bias[cc + 1];
                C[(size_t)r0 * N + cc + 1]       = c[mt][nt][1] + bv;
                C[(size_t)(r0 + 8) * N + cc + 1] = c[mt][nt][3] + bv;
            }
        }
    }
}

// ========== fused two-layer pipelined GRU recurrence (128 CTAs, persistent) =====
// CTA = (bg 0..1, og 0..63): 8 outputs x 16 batches, BOTH layers.
// vt = 0..128: layer-0 does step vt (vt<128), layer-1 does step vt-1 (vt>0).
// Layer-1 input projection folded as concat dot [y0; h1] . [Wx1col; U1col].
#define HST 1028          // hS / W1 row stride (floats)
#define W0ST 516          // W0 row stride
__global__ __launch_bounds__(256)
void recur_fused(const float* __restrict__ A,     // layer-0 ax [S,32,1536]
                 const float* __restrict__ U,     // [2,3,512,512]
                 const float* __restrict__ Wx,    // [2,3,512,512]
                 const float* __restrict__ bx,    // [2,3,512]
                 const float* __restrict__ h0in,  // [2,32,512]
                 float* __restrict__ Y,           // tops [S,32,512]
                 float* __restrict__ hfin) {      // [2,32,512]
    extern __shared__ float smem[];
    float* W0    = smem;                          // 24 x 516  (r,z,c gates x 8 o)
    float* W1    = W0 + 24 * W0ST;                // 24 x 1028 (concat Wx1|U1)
    float* hS    = W1 + 24 * HST;                 // 16 b x 1028: [h0prev | h1prev/rh]
    float* redS  = hS + 16 * HST;                 // 32 x 34 (p1) / 8 x 68 (p2)
    float* zS    = redS + 32 * 34;                // 16 x 17 (L*8+ol)
    float* holdS = zS + 16 * 17;                  // 16 x 17

    const int tid = threadIdx.x, lane = tid & 31, w = tid >> 5;
    const int og = blockIdx.x & 63, bg = blockIdx.x >> 6;
    const int bgrp = og >> 3;                     // barrier group (8 CTAs)
    const int o0 = og * 8;

    // p1 compute roles
    const int q = w & 1, rg = w >> 1;             // rg: 0 L0r 1 L0z 2 L1r 3 L1z
    const int gr = rg & 1;
    const int bl = lane & 15, slot = lane >> 4;   // 16 batches x 2 row-slots
    // p1/p2 finalize roles
    const int frow = tid >> 4, fb = tid & 15;     // frow 0..15, fb 0..15
    const int fo = o0 + (frow & 7);
    const int fbglob = bg * 16 + fb;
    // p2 compute roles
    const int q2 = w & 3, sh = w >> 2;            // k-quarter x row-half

    // ---- stage weights (once) ----
    for (int idx = tid; idx < 12288; idx += 256) {
        int g = idx >> 12, r = idx & 4095, k = r >> 3, ol = r & 7;
        W0[(g * 8 + ol) * W0ST + k] =
            U[(size_t)g * 262144 + (size_t)k * 512 + o0 + ol];
    }
    for (int idx = tid; idx < 24576; idx += 256) {
        int g = idx >> 13, r = idx & 8191, k = r >> 3, ol = r & 7;
        float v;
        if (k < 512) v = Wx[(size_t)(3 + g) * 262144 + (size_t)k * 512 + o0 + ol];
        else         v = U[(size_t)(3 + g) * 262144 + (size_t)(k - 512) * 512 + o0 + ol];
        W1[(g * 8 + ol) * HST + k] = v;
    }

    // constant bias loads (layer 1)
    float av1b = __ldg(&bx[(size_t)(3 + (frow >> 3)) * 512 + fo]);
    float av2b = (tid < 128) ? __ldg(&bx[(size_t)5 * 512 + o0 + (tid >> 4)]) : 0.f;

    // ---- seed h states (og==0 CTA per bg) ----
    if (og == 0) {
        for (int i = tid; i < 2048; i += 256) {
            int b = i >> 7, f = i & 127;
            float4 v0 = *(const float4*)(h0in + (size_t)(bg * 16 + b) * 512 + f * 4);
            float4 v1 = *(const float4*)(h0in + 16384 + (size_t)(bg * 16 + b) * 512 + f * 4);
            __stcg((float4*)(g_h0 + (size_t)(bg * 16 + b) * 512 + f * 4), v0);
            __stcg((float4*)(g_h1 + (size_t)(bg * 16 + b) * 512 + f * 4), v1);
        }
    }
    bg_barrier(bg, bgrp);

    for (int vt = 0; vt <= S_LEN; ++vt) {
        const bool l0 = (vt < S_LEN);
        const bool l1 = (vt > 0);
        const int t1 = vt - 1;

        // prefetch layer-0 A operands for finalize roles
        float av1a = 0.f, av2a = 0.f;
        if (l0) {
            av1a = __ldg(&A[((size_t)vt * 32 + fbglob) * 1536 + (frow >> 3) * 512 + fo]);
            if (tid < 128)
                av2a = __ldg(&A[((size_t)vt * 32 + fbglob) * 1536 + 1024 + o0 + (tid >> 4)]);
        }

        // ---- stage h0prev and h1prev ----
        for (int i = tid; i < 2048; i += 256) {
            int b = i >> 7, f = i & 127;
            *(float4*)&hS[b * HST + f * 4] =
                __ldcg((const float4*)(g_h0 + (size_t)(bg * 16 + b) * 512 + f * 4));
        }
        if (l1) {
            for (int i = tid; i < 2048; i += 256) {
                int b = i >> 7, f = i & 127;
                *(float4*)&hS[b * HST + 512 + f * 4] =
                    __ldcg((const float4*)(g_h1 + (size_t)(bg * 16 + b) * 512 + f * 4));
            }
        }
        __syncthreads();

        // ---- phase 1 compute ----
        if (rg < 2) {
            if (l0) {
                const float* hp = hS + bl * HST + q * 256;
                const float* up = W0 + (gr * 8 + slot * 4) * W0ST + q * 256;
                u64 a0 = 0ull, a1 = 0ull, a2 = 0ull, a3 = 0ull;
                #pragma unroll 4
                for (int c = 0; c < 64; c++) {
                    ulonglong2 hv = *(const ulonglong2*)(hp + c * 4);
                    ulonglong2 u0 = *(const ulonglong2*)(up + c * 4);
                    ulonglong2 u1 = *(const ulonglong2*)(up + W0ST + c * 4);
                    ulonglong2 u2 = *(const ulonglong2*)(up + 2 * W0ST + c * 4);
                    ulonglong2 u3 = *(const ulonglong2*)(up + 3 * W0ST + c * 4);
                    fma2(a0, hv.x, u0.x); fma2(a1, hv.x, u1.x);
                    fma2(a2, hv.x, u2.x); fma2(a3, hv.x, u3.x);
                    fma2(a0, hv.y, u0.y); fma2(a1, hv.y, u1.y);
                    fma2(a2, hv.y, u2.y); fma2(a3, hv.y, u3.y);
                }
                int row = rg * 8 + slot * 4;
                redS[(row + 0) * 34 + bl * 2 + q] = acc_sum(a0);
                redS[(row + 1) * 34 + bl * 2 + q] = acc_sum(a1);
                redS[(row + 2) * 34 + bl * 2 + q] = acc_sum(a2);
                redS[(row + 3) * 34 + bl * 2 + q] = acc_sum(a3);
            }
        } else {
            if (l1) {
                const float* hp = hS + bl * HST + q * 512;
                const float* up = W1 + (gr * 8 + slot * 4) * HST + q * 512;
                u64 a0 = 0ull, a1 = 0ull, a2 = 0ull, a3 = 0ull;
                #pragma unroll 4
                for (int c = 0; c < 128; c++) {
                    ulonglong2 hv = *(const ulonglong2*)(hp + c * 4);
                    ulonglong2 u0 = *(const ulonglong2*)(up + c * 4);
                    ulonglong2 u1 = *(const ulonglong2*)(up + HST + c * 4);
                    ulonglong2 u2 = *(const ulonglong2*)(up + 2 * HST + c * 4);
                    ulonglong2 u3 = *(const ulonglong2*)(up + 3 * HST + c * 4);
                    fma2(a0, hv.x, u0.x); fma2(a1, hv.x, u1.x);
                    fma2(a2, hv.x, u2.x); fma2(a3, hv.x, u3.x);
                    fma2(a0, hv.y, u0.y); fma2(a1, hv.y, u1.y);
                    fma2(a2, hv.y, u2.y); fma2(a3, hv.y, u3.y);
                }
                int row = rg * 8 + slot * 4;
                redS[(row + 0) * 34 + bl * 2 + q] = acc_sum(a0);
                redS[(row + 1) * 34 + bl * 2 + q] = acc_sum(a1);
                redS[(row + 2) * 34 + bl * 2 + q] = acc_sum(a2);
                redS[(row + 3) * 34 + bl * 2 + q] = acc_sum(a3);
            }
        }
        __syncthreads();

        // ---- phase 1 finalize ----
        if (l0) {
            float s = redS[frow * 34 + fb * 2] + redS[frow * 34 + fb * 2 + 1] + av1a;
            float sg = 1.f / (1.f + __expf(-s));
            if (frow < 8) {
                float hold = hS[fb * HST + fo];
                holdS[frow * 17 + fb] = hold;
                __stcg(&g_rh0[(size_t)fbglob * 512 + fo], sg * hold);
            } else {
                zS[(frow - 8) * 17 + fb] = sg;
            }
        }
        if (l1) {
            int row1 = 16 + frow;
            float s = redS[row1 * 34 + fb * 2] + redS[row1 * 34 + fb * 2 + 1] + av1b;
            float sg = 1.f / (1.f + __expf(-s));
            if (frow < 8) {
                float hold = hS[fb * HST + 512 + fo];
                holdS[(8 + frow) * 17 + fb] = hold;
                __stcg(&g_rh1[(size_t)fbglob * 512 + fo], sg * hold);
            } else {
                zS[(8 + frow - 8) * 17 + fb] = sg;
            }
        }
        bg_barrier(bg, bgrp);

        // ---- stage rh0 into second slot ----
        if (l0) {
            for (int i = tid; i < 2048; i += 256) {
                int b = i >> 7, f = i & 127;
                *(float4*)&hS[b * HST + 512 + f * 4] =
                    __ldcg((const float4*)(g_rh0 + (size_t)(bg * 16 + b) * 512 + f * 4));
            }
        }
        __syncthreads();

        // ---- phase 2 L0 compute ----
        if (l0) {
            #pragma unroll
            for (int j = 0; j < 2; j++) {
                int ol = sh * 4 + slot * 2 + j;
                const float* hp = hS + bl * HST + 512 + q2 * 128;
                const float* up = W0 + (16 + ol) * W0ST + q2 * 128;
                u64 a0 = 0ull, a1 = 0ull;
                #pragma unroll 4
                for (int c = 0; c < 32; c++) {
                    ulonglong2 hv = *(const ulonglong2*)(hp + c * 4);
                    ulonglong2 uv = *(const ulonglong2*)(up + c * 4);
                    fma2(a0, hv.x, uv.x); fma2(a1, hv.y, uv.y);
                }
                redS[ol * 68 + bl * 4 + q2] = acc_sum(a0) + acc_sum(a1);
            }
        }
        __syncthreads();

        // ---- phase 2 L0 finalize + restage rh1 ----
        if (l0 && tid < 128) {
            int row = tid >> 4;
            float4 p = *(const float4*)&redS[row * 68 + fb * 4];
            float hh = tanhf((p.x + p.y) + (p.z + p.w) + av2a);
            float z = zS[row * 17 + fb];
            float hold = holdS[row * 17 + fb];
            float hn = fmaf(z, hh - hold, hold);
            __stcg(&g_h0[(size_t)fbglob * 512 + o0 + row], hn);
        }
        if (l1) {
            for (int i = tid; i < 2048; i += 256) {
                int b = i >> 7, f = i & 127;
                *(float4*)&hS[b * HST + 512 + f * 4] =
                    __ldcg((const float4*)(g_rh1 + (size_t)(bg * 16 + b) * 512 + f * 4));
            }
        }
        __syncthreads();

        // ---- phase 2 L1 compute: concat [h0prev | rh1] ----
        if (l1) {
            #pragma unroll
            for (int j = 0; j < 2; j++) {
                int ol = sh * 4 + slot * 2 + j;
                const float* hp = (q2 < 2) ? (hS + bl * HST + q2 * 256)
                                           : (hS + bl * HST + 512 + (q2 - 2) * 256);
                const float* up = W1 + (16 + ol) * HST + q2 * 256;
                u64 a0 = 0ull, a1 = 0ull;
                #pragma unroll 4
                for (int c = 0; c < 64; c++) {
                    ulonglong2 hv = *(const ulonglong2*)(hp + c * 4);
                    ulonglong2 uv = *(const ulonglong2*)(up + c * 4);
                    fma2(a0, hv.x, uv.x); fma2(a1, hv.y, uv.y);
                }
                redS[ol * 68 + bl * 4 + q2] = acc_sum(a0) + acc_sum(a1);
            }
        }
        __syncthreads();

        // ---- phase 2 L1 finalize ----
        if (l1 && tid < 128) {
            int row = tid >> 4;
            float4 p = *(const float4*)&redS[row * 68 + fb * 4];
            float hh = tanhf((p.x + p.y) + (p.z + p.w) + av2b);
            float z = zS[(8 + row) * 17 + fb];
            float hold = holdS[(8 + row) * 17 + fb];
            float hn = fmaf(z, hh - hold, hold);
            __stcg(&g_h1[(size_t)fbglob * 512 + o0 + row], hn);
            __stcg(&Y[((size_t)t1 * 32 + fbglob) * 512 + o0 + row], hn);
        }
        bg_barrier(bg, bgrp);
    }

    // ---- final hidden states ----
    if (og == 0) {
        for (int i = tid; i < 2048; i += 256) {
            int b = i >> 7, f = i & 127;
            float4 v0 = __ldcg((const float4*)(g_h0 + (size_t)(bg * 16 + b) * 512 + f * 4));
            float4 v1 = __ldcg((const float4*)(g_h1 + (size_t)(bg * 16 + b) * 512 + f * 4));
            *(float4*)(hfin + (size_t)(bg * 16 + b) * 512 + f * 4) = v0;
            *(float4*)(hfin + 16384 + (size_t)(bg * 16 + b) * 512 + f * 4) = v1;
        }
    }
}

// ---------------- launch ----------------
extern "C" void kernel_launch(void* const* d_in, const int* in_sizes, int n_in,
                              void* d_out, int out_size) {
    const void*  tokens = d_in[0];
    const float* h0  = (const float*)d_in[1];
    const float* emb = (const float*)d_in[2];
    const float* Wx  = (const float*)d_in[3];
    const float* bx  = (const float*)d_in[4];
    const float* U   = (const float*)d_in[5];
    const float* Wy  = (const float*)d_in[6];
    const float* by  = (const float*)d_in[7];

    float* logits = (float*)d_out;                              // [S,B,V]
    float* hfin   = logits + (size_t)S_LEN * B_SZ * V_SZ;       // [L,B,H]

    float *dX, *dA;
    cudaGetSymbolAddress((void**)&dX, g_X);
    cudaGetSymbolAddress((void**)&dA, g_A);

    const int M = S_LEN * B_SZ;
    const int RSMEM = (24 * W0ST + 24 * HST + 16 * HST + 32 * 34 + 2 * 16 * 17) * 4;
    cudaFuncSetAttribute(recur_fused, cudaFuncAttributeMaxDynamicSharedMemorySize, RSMEM);
    const int GSMEM = 6 * GBUF * 4;
    cudaFuncSetAttribute(gemm_bt, cudaFuncAttributeMaxDynamicSharedMemorySize, GSMEM);

    dim3 blk(256);

    detect_kernel<<<1, 32>>>((const int*)tokens);
    embed_kernel<<<M, 128>>>(tokens, emb, dX);

    // A0 = X @ Wx[0] + bx[0] (layer 0 only)
    gemm_ax<<<dim3(12, M / 128), blk>>>(dX, Wx, bx, dA);

    // fused two-layer pipelined recurrence -> tops into dX, finals into hfin
    recur_fused<<<128, 256, RSMEM>>>(dA, U, Wx, bx, h0, dX, hfin);

    // pre-round operands to tf32 (tops in place; Wy -> g_A, dead after recurrence)
    round_tf32_kernel<<<1184, 256>>>((float4*)dX, (const float4*)Wy, (float4*)dA);

    // logits = round(tops) @ round(Wy)^T + by
    gemm_bt<<<dim3((V_SZ + 127) / 128, M / 128), blk, GSMEM>>>(dX, dA, by, logits, V_SZ);
}

// round 14
// speedup vs baseline: 1.7292x; 1.7292x over previous
#include <cuda_runtime.h>
#include <cstdint>

#define S_LEN 128
#define B_SZ  32
#define H_DIM 512
#define V_SZ  10000

typedef unsigned long long u64;

// ---------------- scratch (device globals; no allocation allowed) ----------------
__device__ float g_X[S_LEN * B_SZ * H_DIM];       // layer input / tops (8 MB)
__device__ float g_A[S_LEN * B_SZ * 3 * H_DIM];   // ax scratch / rounded Wy (24 MB)
__device__ float g_h0[B_SZ * H_DIM];              // layer-0 h
__device__ float g_h1[B_SZ * H_DIM];              // layer-1 h
__device__ float g_rh0[B_SZ * H_DIM];             // layer-0 r*h
__device__ float g_rh1[B_SZ * H_DIM];             // layer-1 r*h
__device__ int   g_is64;

// ---------------- per-domain grid barrier (2 domains x 64 CTAs, flat R11) --------
__device__ unsigned          g_cnt2[2 * 32];
__device__ volatile unsigned g_gen2[2 * 32];

__device__ __forceinline__ void bg_barrier(int bg) {
    __syncthreads();
    if (threadIdx.x == 0) {
        volatile unsigned* genp = &g_gen2[bg * 32];
        unsigned* cntp = &g_cnt2[bg * 32];
        unsigned gen = *genp;
        __threadfence();
        if (atomicAdd(cntp, 1u) == 63u) {
            *cntp = 0;
            __threadfence();
            *genp = gen + 1;
        } else {
            unsigned it = 0;
            while (*genp == gen) {
                if (++it > 65536u) { __nanosleep(32); }
                if (it > 400000u) break;   // safety valve: never hang
            }
        }
        __threadfence();
    }
    __syncthreads();
}

// ---------------- token dtype detector ----------------
__global__ void detect_kernel(const int* __restrict__ t32) {
    if (threadIdx.x == 0 && blockIdx.x == 0) {
        unsigned o = 0;
        for (int i = 0; i < 128; i++) o |= (unsigned)t32[2 * i + 1];
        g_is64 = (o == 0) ? 1 : 0;
    }
}

// ---------------- embedding gather (dtype-robust, clamped) ----------------
__global__ void embed_kernel(const void* __restrict__ tok,
                             const float* __restrict__ emb,
                             float* __restrict__ X) {
    int row = blockIdx.x;
    long long t;
    if (g_is64) t = ((const long long*)tok)[row];
    else        t = (long long)((const int*)tok)[row];
    if (t < 0) t = 0;
    if (t >= V_SZ) t = V_SZ - 1;
    const float4* src = (const float4*)(emb + (size_t)t * H_DIM);
    float4* dst = (float4*)(X + (size_t)row * H_DIM);
    for (int i = threadIdx.x; i < H_DIM / 4; i += blockDim.x) dst[i] = src[i];
}

// ---------------- tf32 mma + cp.async helpers ----------------
#define BM 128
#define BN 128
#define BKK 16
#define AST 20
#define BST_KN 136
#define BST_NK 20

__device__ __forceinline__ unsigned f2tf(float x) {
    unsigned r; asm("cvt.rna.tf32.f32 %0, %1;" : "=r"(r) : "f"(x)); return r;
}
__device__ __forceinline__ void mma8(float* c, const unsigned* a, const unsigned* b) {
    asm volatile(
        "mma.sync.aligned.m16n8k8.row.col.f32.tf32.tf32.f32 "
        "{%0,%1,%2,%3}, {%4,%5,%6,%7}, {%8,%9}, {%0,%1,%2,%3};\n"
        : "+f"(c[0]), "+f"(c[1]), "+f"(c[2]), "+f"(c[3])
        : "r"(a[0]), "r"(a[1]), "r"(a[2]), "r"(a[3]), "r"(b[0]), "r"(b[1]));
}
__device__ __forceinline__ void cpa16(unsigned dst, const void* src, bool pred) {
    int sz = pred ? 16 : 0;
    asm volatile("cp.async.cg.shared.global [%0], [%1], 16, %2;\n"
                 :: "r"(dst), "l"(src), "r"(sz));
}
__device__ __forceinline__ void cpa_commit() {
    asm volatile("cp.async.commit_group;\n" ::: "memory");
}
__device__ __forceinline__ void cpa_wait1() {
    asm volatile("cp.async.wait_group 1;\n" ::: "memory");
}
__device__ __forceinline__ unsigned smem_u32(const void* p) {
    return (unsigned)__cvta_generic_to_shared(p);
}
__device__ __forceinline__ void fma2(u64& acc, u64 a, u64 b) {
    asm("fma.rn.f32x2 %0, %1, %2, %0;" : "+l"(acc) : "l"(a), "l"(b));
}
__device__ __forceinline__ float acc_sum(u64 a) {
    unsigned lo, hi;
    asm("mov.b64 {%0,%1}, %2;" : "=r"(lo), "=r"(hi) : "l"(a));
    return __uint_as_float(lo) + __uint_as_float(hi);
}

// ---------------- tf32 pre-rounding kernel (tops in-place, Wy -> Wyr) -----------
#define TOPS_N4 (S_LEN * B_SZ * H_DIM / 4)   // 524288
#define WY_N4   (V_SZ * H_DIM / 4)           // 1280000
__global__ void round_tf32_kernel(float4* __restrict__ X,
                                  const float4* __restrict__ Wy,
                                  float4* __restrict__ Wyr) {
    int stride = gridDim.x * blockDim.x;
    int start = blockIdx.x * blockDim.x + threadIdx.x;
    for (int i = start; i < WY_N4; i += stride) {
        float4 v = Wy[i];
        v.x = __uint_as_float(f2tf(v.x)); v.y = __uint_as_float(f2tf(v.y));
        v.z = __uint_as_float(f2tf(v.z)); v.w = __uint_as_float(f2tf(v.w));
        Wyr[i] = v;
    }
    for (int i = start; i < TOPS_N4; i += stride) {
        float4 v = X[i];
        v.x = __uint_as_float(f2tf(v.x)); v.y = __uint_as_float(f2tf(v.y));
        v.z = __uint_as_float(f2tf(v.z)); v.w = __uint_as_float(f2tf(v.w));
        X[i] = v;
    }
}

// ---------- fused 3-gate input GEMM for layer 0 (2-stage cp.async) --------------
__global__ __launch_bounds__(256, 2)
void gemm_ax(const float* __restrict__ A,          // X [M,512]
             const float* __restrict__ Wxl,        // [3,512,512]
             const float* __restrict__ bxl,        // [3,512]
             float* __restrict__ C) {              // [M,1536]
    __shared__ float As[2][BM * AST];
    __shared__ float Bs[2][BKK * BST_KN];

    int tid = threadIdx.x;
    int lane = tid & 31, warp = tid >> 5;
    int wr = warp >> 2, wc = warp & 3;
    int m0 = blockIdx.y * BM, n0 = blockIdx.x * BN;
    int g = n0 >> 9, col0 = n0 & 511;
    const float* Bg = Wxl + (size_t)g * H_DIM * H_DIM;

    const int ra = tid >> 1, ha = tid & 1;
    const int krb = tid >> 4, csb = tid & 15;
    const float* Asrc = A + (size_t)(m0 + ra) * H_DIM + ha * 8;
    const float* Bsrc = Bg + (size_t)krb * H_DIM + col0 + csb * 8;

    float c[4][4][4];
    #pragma unroll
    for (int i = 0; i < 4; i++)
        #pragma unroll
        for (int j = 0; j < 4; j++)
            #pragma unroll
            for (int k = 0; k < 4; k++) c[i][j][k] = 0.f;

    const int NK = H_DIM / BKK;
    {
        unsigned da0 = smem_u32(&As[0][ra * AST + ha * 8]);
        cpa16(da0, Asrc, true); cpa16(da0 + 16, Asrc + 4, true);
        unsigned db0 = smem_u32(&Bs[0][krb * BST_KN + csb * 8]);
        cpa16(db0, Bsrc, true); cpa16(db0 + 16, Bsrc + 4, true);
        cpa_commit();
    }

    for (int it = 0; it < NK; it++) {
        if (it + 1 < NK) {
            int kk = (it + 1) * BKK, buf = (it + 1) & 1;
            unsigned da = smem_u32(&As[buf][ra * AST + ha * 8]);
            cpa16(da, Asrc + kk, true); cpa16(da + 16, Asrc + kk + 4, true);
            unsigned db = smem_u32(&Bs[buf][krb * BST_KN + csb * 8]);
            cpa16(db, Bsrc + (size_t)kk * H_DIM, true);
            cpa16(db + 16, Bsrc + (size_t)kk * H_DIM + 4, true);
        }
        cpa_commit();
        cpa_wait1();
        __syncthreads();

        const float* Ab = As[it & 1];
        const float* Bb = Bs[it & 1];
        int ar = lane >> 2, ak = lane & 3;
        #pragma unroll
        for (int kq = 0; kq < BKK; kq += 8) {
            unsigned af[4][4], bf[4][2];
            #pragma unroll
            for (int mt = 0; mt < 4; mt++) {
                int rb = wr * 64 + mt * 16;
                af[mt][0] = f2tf(Ab[(rb + ar)     * AST + kq + ak]);
                af[mt][1] = f2tf(Ab[(rb + ar + 8) * AST + kq + ak]);
                af[mt][2] = f2tf(Ab[(rb + ar)     * AST + kq + ak + 4]);
                af[mt][3] = f2tf(Ab[(rb + ar + 8) * AST + kq + ak + 4]);
            }
            #pragma unroll
            for (int nt = 0; nt < 4; nt++) {
                int cb = wc * 32 + nt * 8 + (lane >> 2);
                bf[nt][0] = f2tf(Bb[(kq + ak)     * BST_KN + cb]);
                bf[nt][1] = f2tf(Bb[(kq + ak + 4) * BST_KN + cb]);
            }
            #pragma unroll
            for (int mt = 0; mt < 4; mt++)
                #pragma unroll
                for (int nt = 0; nt < 4; nt++)
                    mma8(c[mt][nt], af[mt], bf[nt]);
        }
        __syncthreads();
    }

    #pragma unroll
    for (int mt = 0; mt < 4; mt++) {
        #pragma unroll
        for (int nt = 0; nt < 4; nt++) {
            int r0 = m0 + wr * 64 + mt * 16 + (lane >> 2);
            int cc = n0 + wc * 32 + nt * 8 + (lane & 3) * 2;
            float bv0 = bxl[g * H_DIM + (cc & 511)];
            float bv1 = bxl[g * H_DIM + ((cc + 1) & 511)];
            C[(size_t)r0 * 1536 + cc]           = c[mt][nt][0] + bv0;
            C[(size_t)r0 * 1536 + cc + 1]       = c[mt][nt][1] + bv1;
            C[(size_t)(r0 + 8) * 1536 + cc]     = c[mt][nt][2] + bv0;
            C[(size_t)(r0 + 8) * 1536 + cc + 1] = c[mt][nt][3] + bv1;
        }
    }
}

// ------- logits GEMM, 3-stage cp.async; operands PRE-ROUNDED to tf32 -----------
#define GBUF 2560
__global__ __launch_bounds__(256, 2)
void gemm_bt(const float* __restrict__ A,
             const float* __restrict__ Bm,
             const float* __restrict__ bias,
             float* __restrict__ C, int N) {
    extern __shared__ float sm[];
    float* AsB = sm;
    float* BsB = sm + 3 * GBUF;

    int tid = threadIdx.x;
    int lane = tid & 31, warp = tid >> 5;
    int wr = warp >> 2, wc = warp & 3;
    int m0 = blockIdx.y * BM, n0 = blockIdx.x * BN;

    const int ra = tid >> 1, ha = tid & 1;
    const int gn = n0 + ra;
    const bool bok = (gn < N);
    const float* Asrc = A + (size_t)(m0 + ra) * H_DIM + ha * 8;
    const float* Bsrc = Bm + (size_t)(bok ? gn : 0) * H_DIM + ha * 8;

    float c[4][4][4];
    #pragma unroll
    for (int i = 0; i < 4; i++)
        #pragma unroll
        for (int j = 0; j < 4; j++)
            #pragma unroll
            for (int k = 0; k < 4; k++) c[i][j][k] = 0.f;

    const int NK = H_DIM / BKK;
    #pragma unroll
    for (int s = 0; s < 2; s++) {
        int kk = s * BKK;
        unsigned da = smem_u32(&AsB[s * GBUF + ra * AST + ha * 8]);
        cpa16(da, Asrc + kk, true); cpa16(da + 16, Asrc + kk + 4, true);
        unsigned db = smem_u32(&BsB[s * GBUF + ra * BST_NK + ha * 8]);
        cpa16(db, Bsrc + kk, bok); cpa16(db + 16, Bsrc + kk + 4, bok);
        cpa_commit();
    }

    int buf = 0;
    for (int it = 0; it < NK; it++) {
        cpa_wait1();
        __syncthreads();

        const float* Ab = &AsB[buf * GBUF];
        const float* Bb = &BsB[buf * GBUF];
        int ar = lane >> 2, ak = lane & 3;
        #pragma unroll
        for (int kq = 0; kq < BKK; kq += 8) {
            unsigned af[4][4], bf[4][2];
            #pragma unroll
            for (int mt = 0; mt < 4; mt++) {
                int rb = wr * 64 + mt * 16;
                af[mt][0] = __float_as_uint(Ab[(rb + ar)     * AST + kq + ak]);
                af[mt][1] = __float_as_uint(Ab[(rb + ar + 8) * AST + kq + ak]);
                af[mt][2] = __float_as_uint(Ab[(rb + ar)     * AST + kq + ak + 4]);
                af[mt][3] = __float_as_uint(Ab[(rb + ar + 8) * AST + kq + ak + 4]);
            }
            #pragma unroll
            for (int nt = 0; nt < 4; nt++) {
                int cb = wc * 32 + nt * 8 + (lane >> 2);
                bf[nt][0] = __float_as_uint(Bb[cb * BST_NK + kq + ak]);
                bf[nt][1] = __float_as_uint(Bb[cb * BST_NK + kq + ak + 4]);
            }
            #pragma unroll
            for (int mt = 0; mt < 4; mt++)
                #pragma unroll
                for (int nt = 0; nt < 4; nt++)
                    mma8(c[mt][nt], af[mt], bf[nt]);
        }
        __syncthreads();

        if (it + 2 < NK) {
            int kk = (it + 2) * BKK;
            int nb = (it + 2) % 3;
            unsigned da = smem_u32(&AsB[nb * GBUF + ra * AST + ha * 8]);
            cpa16(da, Asrc + kk, true); cpa16(da + 16, Asrc + kk + 4, true);
            unsigned db = smem_u32(&BsB[nb * GBUF + ra * BST_NK + ha * 8]);
            cpa16(db, Bsrc + kk, bok); cpa16(db + 16, Bsrc + kk + 4, bok);
        }
        cpa_commit();
        buf = (buf + 1) % 3;
    }

    #pragma unroll
    for (int mt = 0; mt < 4; mt++) {
        #pragma unroll
        for (int nt = 0; nt < 4; nt++) {
            int r0 = m0 + wr * 64 + mt * 16 + (lane >> 2);
            int cc = n0 + wc * 32 + nt * 8 + (lane & 3) * 2;
            if (cc < N) {
                float bv = bias[cc];
                C[(size_t)r0 * N + cc]       = c[mt][nt][0] + bv;
                C[(size_t)(r0 + 8) * N + cc] = c[mt][nt][2] + bv;
            }
            if (cc + 1 < N) {
                float bv = bias[cc + 1];
                C[(size_t)r0 * N + cc + 1]       = c[mt][nt][1] + bv;
                C[(size_t)(r0 + 8) * N + cc + 1] = c[mt][nt][3] + bv;
            }
        }
    }
}

// ========== fused two-layer pipelined GRU recurrence (128 CTAs, persistent) =====
// CTA = (bg 0..1, og 0..63): 8 outputs x 16 batches, BOTH layers.
// vt = 0..128: layer-0 does step vt (vt<128), layer-1 does step vt-1 (vt>0).
// Layer-1 input projection folded as concat dot [y0; h1] . [Wx1col; U1col].
#define HST 1028          // hS / W1 row stride (floats)
#define W0ST 516          // W0 row stride
__global__ __launch_bounds__(256)
void recur_fused(const float* __restrict__ A,     // layer-0 ax [S,32,1536]
                 const float* __restrict__ U,     // [2,3,512,512]
                 const float* __restrict__ Wx,    // [2,3,512,512]
                 const float* __restrict__ bx,    // [2,3,512]
                 const float* __restrict__ h0in,  // [2,32,512]
                 float* __restrict__ Y,           // tops [S,32,512]
                 float* __restrict__ hfin) {      // [2,32,512]
    extern __shared__ float smem[];
    float* W0    = smem;                          // 24 x 516  (r,z,c gates x 8 o)
    float* W1    = W0 + 24 * W0ST;                // 24 x 1028 (concat Wx1|U1)
    float* hS    = W1 + 24 * HST;                 // 16 b x 1028: [h0prev | h1prev/rh]
    float* redS  = hS + 16 * HST;                 // 32 x 34 (p1) / 8 x 68 (p2)
    float* zS    = redS + 32 * 34;                // 16 x 17 (L*8+ol)
    float* holdS = zS + 16 * 17;                  // 16 x 17

    const int tid = threadIdx.x, lane = tid & 31, w = tid >> 5;
    const int og = blockIdx.x & 63, bg = blockIdx.x >> 6;
    const int o0 = og * 8;

    // p1 compute roles
    const int q = w & 1, rg = w >> 1;             // rg: 0 L0r 1 L0z 2 L1r 3 L1z
    const int gr = rg & 1;
    const int bl = lane & 15, slot = lane >> 4;   // 16 batches x 2 row-slots
    // p1/p2 finalize roles
    const int frow = tid >> 4, fb = tid & 15;     // frow 0..15, fb 0..15
    const int fo = o0 + (frow & 7);
    const int fbglob = bg * 16 + fb;
    // p2 compute roles
    const int q2 = w & 3, sh = w >> 2;            // k-quarter x row-half

    // ---- stage weights (once) ----
    for (int idx = tid; idx < 12288; idx += 256) {
        int g = idx >> 12, r = idx & 4095, k = r >> 3, ol = r & 7;
        W0[(g * 8 + ol) * W0ST + k] =
            U[(size_t)g * 262144 + (size_t)k * 512 + o0 + ol];
    }
    for (int idx = tid; idx < 24576; idx += 256) {
        int g = idx >> 13, r = idx & 8191, k = r >> 3, ol = r & 7;
        float v;
        if (k < 512) v = Wx[(size_t)(3 + g) * 262144 + (size_t)k * 512 + o0 + ol];
        else         v = U[(size_t)(3 + g) * 262144 + (size_t)(k - 512) * 512 + o0 + ol];
        W1[(g * 8 + ol) * HST + k] = v;
    }

    // constant bias loads (layer 1)
    float av1b = __ldg(&bx[(size_t)(3 + (frow >> 3)) * 512 + fo]);
    float av2b = (tid < 128) ? __ldg(&bx[(size_t)5 * 512 + o0 + (tid >> 4)]) : 0.f;

    // ---- seed h states (og==0 CTA per bg) ----
    if (og == 0) {
        for (int i = tid; i < 2048; i += 256) {
            int b = i >> 7, f = i & 127;
            float4 v0 = *(const float4*)(h0in + (size_t)(bg * 16 + b) * 512 + f * 4);
            float4 v1 = *(const float4*)(h0in + 16384 + (size_t)(bg * 16 + b) * 512 + f * 4);
            __stcg((float4*)(g_h0 + (size_t)(bg * 16 + b) * 512 + f * 4), v0);
            __stcg((float4*)(g_h1 + (size_t)(bg * 16 + b) * 512 + f * 4), v1);
        }
    }
    bg_barrier(bg);

    for (int vt = 0; vt <= S_LEN; ++vt) {
        const bool l0 = (vt < S_LEN);
        const bool l1 = (vt > 0);
        const int t1 = vt - 1;

        // prefetch layer-0 A operands for finalize roles
        float av1a = 0.f, av2a = 0.f;
        if (l0) {
            av1a = __ldg(&A[((size_t)vt * 32 + fbglob) * 1536 + (frow >> 3) * 512 + fo]);
            if (tid < 128)
                av2a = __ldg(&A[((size_t)vt * 32 + fbglob) * 1536 + 1024 + o0 + (tid >> 4)]);
        }

        // ---- stage h0prev and h1prev ----
        for (int i = tid; i < 2048; i += 256) {
            int b = i >> 7, f = i & 127;
            *(float4*)&hS[b * HST + f * 4] =
                __ldcg((const float4*)(g_h0 + (size_t)(bg * 16 + b) * 512 + f * 4));
        }
        if (l1) {
            for (int i = tid; i < 2048; i += 256) {
                int b = i >> 7, f = i & 127;
                *(float4*)&hS[b * HST + 512 + f * 4] =
                    __ldcg((const float4*)(g_h1 + (size_t)(bg * 16 + b) * 512 + f * 4));
            }
        }
        __syncthreads();

        // ---- phase 1 compute ----
        if (rg < 2) {
            if (l0) {
                const float* hp = hS + bl * HST + q * 256;
                const float* up = W0 + (gr * 8 + slot * 4) * W0ST + q * 256;
                u64 a0 = 0ull, a1 = 0ull, a2 = 0ull, a3 = 0ull;
                #pragma unroll 4
                for (int c = 0; c < 64; c++) {
                    ulonglong2 hv = *(const ulonglong2*)(hp + c * 4);
                    ulonglong2 u0 = *(const ulonglong2*)(up + c * 4);
                    ulonglong2 u1 = *(const ulonglong2*)(up + W0ST + c * 4);
                    ulonglong2 u2 = *(const ulonglong2*)(up + 2 * W0ST + c * 4);
                    ulonglong2 u3 = *(const ulonglong2*)(up + 3 * W0ST + c * 4);
                    fma2(a0, hv.x, u0.x); fma2(a1, hv.x, u1.x);
                    fma2(a2, hv.x, u2.x); fma2(a3, hv.x, u3.x);
                    fma2(a0, hv.y, u0.y); fma2(a1, hv.y, u1.y);
                    fma2(a2, hv.y, u2.y); fma2(a3, hv.y, u3.y);
                }
                int row = rg * 8 + slot * 4;
                redS[(row + 0) * 34 + bl * 2 + q] = acc_sum(a0);
                redS[(row + 1) * 34 + bl * 2 + q] = acc_sum(a1);
                redS[(row + 2) * 34 + bl * 2 + q] = acc_sum(a2);
                redS[(row + 3) * 34 + bl * 2 + q] = acc_sum(a3);
            }
        } else {
            if (l1) {
                const float* hp = hS + bl * HST + q * 512;
                const float* up = W1 + (gr * 8 + slot * 4) * HST + q * 512;
                u64 a0 = 0ull, a1 = 0ull, a2 = 0ull, a3 = 0ull;
                #pragma unroll 4
                for (int c = 0; c < 128; c++) {
                    ulonglong2 hv = *(const ulonglong2*)(hp + c * 4);
                    ulonglong2 u0 = *(const ulonglong2*)(up + c * 4);
                    ulonglong2 u1 = *(const ulonglong2*)(up + HST + c * 4);
                    ulonglong2 u2 = *(const ulonglong2*)(up + 2 * HST + c * 4);
                    ulonglong2 u3 = *(const ulonglong2*)(up + 3 * HST + c * 4);
                    fma2(a0, hv.x, u0.x); fma2(a1, hv.x, u1.x);
                    fma2(a2, hv.x, u2.x); fma2(a3, hv.x, u3.x);
                    fma2(a0, hv.y, u0.y); fma2(a1, hv.y, u1.y);
                    fma2(a2, hv.y, u2.y); fma2(a3, hv.y, u3.y);
                }
                int row = rg * 8 + slot * 4;
                redS[(row + 0) * 34 + bl * 2 + q] = acc_sum(a0);
                redS[(row + 1) * 34 + bl * 2 + q] = acc_sum(a1);
                redS[(row + 2) * 34 + bl * 2 + q] = acc_sum(a2);
                redS[(row + 3) * 34 + bl * 2 + q] = acc_sum(a3);
            }
        }
        __syncthreads();

        // ---- phase 1 finalize ----
        if (l0) {
            float s = redS[frow * 34 + fb * 2] + redS[frow * 34 + fb * 2 + 1] + av1a;
            float sg = 1.f / (1.f + __expf(-s));
            if (frow < 8) {
                float hold = hS[fb * HST + fo];
                holdS[frow * 17 + fb] = hold;
                __stcg(&g_rh0[(size_t)fbglob * 512 + fo], sg * hold);
            } else {
                zS[(frow - 8) * 17 + fb] = sg;
            }
        }
        if (l1) {
            int row1 = 16 + frow;
            float s = redS[row1 * 34 + fb * 2] + redS[row1 * 34 + fb * 2 + 1] + av1b;
            float sg = 1.f / (1.f + __expf(-s));
            if (frow < 8) {
                float hold = hS[fb * HST + 512 + fo];
                holdS[(8 + frow) * 17 + fb] = hold;
                __stcg(&g_rh1[(size_t)fbglob * 512 + fo], sg * hold);
            } else {
                zS[(8 + frow - 8) * 17 + fb] = sg;
            }
        }
        bg_barrier(bg);

        // ---- stage rh0 into second slot ----
        if (l0) {
            for (int i = tid; i < 2048; i += 256) {
                int b = i >> 7, f = i & 127;
                *(float4*)&hS[b * HST + 512 + f * 4] =
                    __ldcg((const float4*)(g_rh0 + (size_t)(bg * 16 + b) * 512 + f * 4));
            }
        }
        __syncthreads();

        // ---- phase 2 L0 compute ----
        if (l0) {
            #pragma unroll
            for (int j = 0; j < 2; j++) {
                int ol = sh * 4 + slot * 2 + j;
                const float* hp = hS + bl * HST + 512 + q2 * 128;
                const float* up = W0 + (16 + ol) * W0ST + q2 * 128;
                u64 a0 = 0ull, a1 = 0ull;
                #pragma unroll 4
                for (int c = 0; c < 32; c++) {
                    ulonglong2 hv = *(const ulonglong2*)(hp + c * 4);
                    ulonglong2 uv = *(const ulonglong2*)(up + c * 4);
                    fma2(a0, hv.x, uv.x); fma2(a1, hv.y, uv.y);
                }
                redS[ol * 68 + bl * 4 + q2] = acc_sum(a0) + acc_sum(a1);
            }
        }
        __syncthreads();

        // ---- phase 2 L0 finalize + restage rh1 ----
        if (l0 && tid < 128) {
            int row = tid >> 4;
            float4 p = *(const float4*)&redS[row * 68 + fb * 4];
            float hh = tanhf((p.x + p.y) + (p.z + p.w) + av2a);
            float z = zS[row * 17 + fb];
            float hold = holdS[row * 17 + fb];
            float hn = fmaf(z, hh - hold, hold);
            __stcg(&g_h0[(size_t)fbglob * 512 + o0 + row], hn);
        }
        if (l1) {
            for (int i = tid; i < 2048; i += 256) {
                int b = i >> 7, f = i & 127;
                *(float4*)&hS[b * HST + 512 + f * 4] =
                    __ldcg((const float4*)(g_rh1 + (size_t)(bg * 16 + b) * 512 + f * 4));
            }
        }
        __syncthreads();

        // ---- phase 2 L1 compute: concat [h0prev | rh1] ----
        if (l1) {
            #pragma unroll
            for (int j = 0; j < 2; j++) {
                int ol = sh * 4 + slot * 2 + j;
                const float* hp = (q2 < 2) ? (hS + bl * HST + q2 * 256)
                                           : (hS + bl * HST + 512 + (q2 - 2) * 256);
                const float* up = W1 + (16 + ol) * HST + q2 * 256;
                u64 a0 = 0ull, a1 = 0ull;
                #pragma unroll 4
                for (int c = 0; c < 64; c++) {
                    ulonglong2 hv = *(const ulonglong2*)(hp + c * 4);
                    ulonglong2 uv = *(const ulonglong2*)(up + c * 4);
                    fma2(a0, hv.x, uv.x); fma2(a1, hv.y, uv.y);
                }
                redS[ol * 68 + bl * 4 + q2] = acc_sum(a0) + acc_sum(a1);
            }
        }
        __syncthreads();

        // ---- phase 2 L1 finalize ----
        if (l1 && tid < 128) {
            int row = tid >> 4;
            float4 p = *(const float4*)&redS[row * 68 + fb * 4];
            float hh = tanhf((p.x + p.y) + (p.z + p.w) + av2b);
            float z = zS[(8 + row) * 17 + fb];
            float hold = holdS[(8 + row) * 17 + fb];
            float hn = fmaf(z, hh - hold, hold);
            __stcg(&g_h1[(size_t)fbglob * 512 + o0 + row], hn);
            __stcg(&Y[((size_t)t1 * 32 + fbglob) * 512 + o0 + row], hn);
        }
        bg_barrier(bg);
    }

    // ---- final hidden states ----
    if (og == 0) {
        for (int i = tid; i < 2048; i += 256) {
            int b = i >> 7, f = i & 127;
            float4 v0 = __ldcg((const float4*)(g_h0 + (size_t)(bg * 16 + b) * 512 + f * 4));
            float4 v1 = __ldcg((const float4*)(g_h1 + (size_t)(bg * 16 + b) * 512 + f * 4));
            *(float4*)(hfin + (size_t)(bg * 16 + b) * 512 + f * 4) = v0;
            *(float4*)(hfin + 16384 + (size_t)(bg * 16 + b) * 512 + f * 4) = v1;
        }
    }
}

// ---------------- launch ----------------
extern "C" void kernel_launch(void* const* d_in, const int* in_sizes, int n_in,
                              void* d_out, int out_size) {
    const void*  tokens = d_in[0];
    const float* h0  = (const float*)d_in[1];
    const float* emb = (const float*)d_in[2];
    const float* Wx  = (const float*)d_in[3];
    const float* bx  = (const float*)d_in[4];
    const float* U   = (const float*)d_in[5];
    const float* Wy  = (const float*)d_in[6];
    const float* by  = (const float*)d_in[7];

    float* logits = (float*)d_out;                              // [S,B,V]
    float* hfin   = logits + (size_t)S_LEN * B_SZ * V_SZ;       // [L,B,H]

    float *dX, *dA;
    cudaGetSymbolAddress((void**)&dX, g_X);
    cudaGetSymbolAddress((void**)&dA, g_A);

    const int M = S_LEN * B_SZ;
    const int RSMEM = (24 * W0ST + 24 * HST + 16 * HST + 32 * 34 + 2 * 16 * 17) * 4;
    cudaFuncSetAttribute(recur_fused, cudaFuncAttributeMaxDynamicSharedMemorySize, RSMEM);
    const int GSMEM = 6 * GBUF * 4;
    cudaFuncSetAttribute(gemm_bt, cudaFuncAttributeMaxDynamicSharedMemorySize, GSMEM);

    dim3 blk(256);

    detect_kernel<<<1, 32>>>((const int*)tokens);
    embed_kernel<<<M, 128>>>(tokens, emb, dX);

    // A0 = X @ Wx[0] + bx[0] (layer 0 only)
    gemm_ax<<<dim3(12, M / 128), blk>>>(dX, Wx, bx, dA);

    // fused two-layer pipelined recurrence -> tops into dX, finals into hfin
    recur_fused<<<128, 256, RSMEM>>>(dA, U, Wx, bx, h0, dX, hfin);

    // pre-round operands to tf32 (tops in place; Wy -> g_A, dead after recurrence)
    round_tf32_kernel<<<1184, 256>>>((float4*)dX, (const float4*)Wy, (float4*)dA);

    // logits = round(tops) @ round(Wy)^T + by
    gemm_bt<<<dim3((V_SZ + 127) / 128, M / 128), blk, GSMEM>>>(dX, dA, by, logits, V_SZ);
}

// round 15
// speedup vs baseline: 2.4673x; 1.4269x over previous
#include <cuda_runtime.h>
#include <cstdint>

#define S_LEN 128
#define B_SZ  32
#define H_DIM 512
#define V_SZ  10000

typedef unsigned long long u64;

// ---------------- scratch (device globals; no allocation allowed) ----------------
__device__ float g_X[S_LEN * B_SZ * H_DIM];       // layer input / tops (8 MB)
__device__ float g_A[S_LEN * B_SZ * 3 * H_DIM];   // ax scratch / rounded Wy (24 MB)
__device__ float g_h0[B_SZ * H_DIM];              // layer-0 h (full fp32 state)
__device__ float g_h1[B_SZ * H_DIM];              // layer-1 h (full fp32 state)
__device__ float g_rh0[B_SZ * H_DIM];             // layer-0 r*h
__device__ float g_rh1[B_SZ * H_DIM];             // layer-1 r*h
__device__ int   g_is64;

// ---------------- per-domain grid barrier (2 domains x 64 CTAs, flat R11) --------
__device__ unsigned          g_cnt2[2 * 32];
__device__ volatile unsigned g_gen2[2 * 32];

__device__ __forceinline__ void bg_barrier(int bg) {
    __syncthreads();
    if (threadIdx.x == 0) {
        volatile unsigned* genp = &g_gen2[bg * 32];
        unsigned* cntp = &g_cnt2[bg * 32];
        unsigned gen = *genp;
        __threadfence();
        if (atomicAdd(cntp, 1u) == 63u) {
            *cntp = 0;
            __threadfence();
            *genp = gen + 1;
        } else {
            unsigned it = 0;
            while (*genp == gen) {
                if (++it > 65536u) { __nanosleep(32); }
                if (it > 400000u) break;   // safety valve: never hang
            }
        }
        __threadfence();
    }
    __syncthreads();
}

// ---------------- token dtype detector ----------------
__global__ void detect_kernel(const int* __restrict__ t32) {
    if (threadIdx.x == 0 && blockIdx.x == 0) {
        unsigned o = 0;
        for (int i = 0; i < 128; i++) o |= (unsigned)t32[2 * i + 1];
        g_is64 = (o == 0) ? 1 : 0;
    }
}

// ---------------- embedding gather (dtype-robust, clamped) ----------------
__global__ void embed_kernel(const void* __restrict__ tok,
                             const float* __restrict__ emb,
                             float* __restrict__ X) {
    int row = blockIdx.x;
    long long t;
    if (g_is64) t = ((const long long*)tok)[row];
    else        t = (long long)((const int*)tok)[row];
    if (t < 0) t = 0;
    if (t >= V_SZ) t = V_SZ - 1;
    const float4* src = (const float4*)(emb + (size_t)t * H_DIM);
    float4* dst = (float4*)(X + (size_t)row * H_DIM);
    for (int i = threadIdx.x; i < H_DIM / 4; i += blockDim.x) dst[i] = src[i];
}

// ---------------- tf32 mma + cp.async helpers ----------------
#define BM 128
#define BN 128
#define BKK 16
#define AST 20
#define BST_KN 136
#define BST_NK 20

__device__ __forceinline__ unsigned f2tf(float x) {
    unsigned r; asm("cvt.rna.tf32.f32 %0, %1;" : "=r"(r) : "f"(x)); return r;
}
__device__ __forceinline__ float f2tff(float x) {
    return __uint_as_float(f2tf(x));
}
__device__ __forceinline__ void mma8(float* c, const unsigned* a, const unsigned* b) {
    asm volatile(
        "mma.sync.aligned.m16n8k8.row.col.f32.tf32.tf32.f32 "
        "{%0,%1,%2,%3}, {%4,%5,%6,%7}, {%8,%9}, {%0,%1,%2,%3};\n"
        : "+f"(c[0]), "+f"(c[1]), "+f"(c[2]), "+f"(c[3])
        : "r"(a[0]), "r"(a[1]), "r"(a[2]), "r"(a[3]), "r"(b[0]), "r"(b[1]));
}
__device__ __forceinline__ void cpa16(unsigned dst, const void* src, bool pred) {
    int sz = pred ? 16 : 0;
    asm volatile("cp.async.cg.shared.global [%0], [%1], 16, %2;\n"
                 :: "r"(dst), "l"(src), "r"(sz));
}
__device__ __forceinline__ void cpa_commit() {
    asm volatile("cp.async.commit_group;\n" ::: "memory");
}
__device__ __forceinline__ void cpa_wait1() {
    asm volatile("cp.async.wait_group 1;\n" ::: "memory");
}
__device__ __forceinline__ unsigned smem_u32(const void* p) {
    return (unsigned)__cvta_generic_to_shared(p);
}

// ---------------- tf32 pre-rounding kernel (tops in-place, Wy -> Wyr) -----------
#define TOPS_N4 (S_LEN * B_SZ * H_DIM / 4)   // 524288
#define WY_N4   (V_SZ * H_DIM / 4)           // 1280000
__global__ void round_tf32_kernel(float4* __restrict__ X,
                                  const float4* __restrict__ Wy,
                                  float4* __restrict__ Wyr) {
    int stride = gridDim.x * blockDim.x;
    int start = blockIdx.x * blockDim.x + threadIdx.x;
    for (int i = start; i < WY_N4; i += stride) {
        float4 v = Wy[i];
        v.x = f2tff(v.x); v.y = f2tff(v.y); v.z = f2tff(v.z); v.w = f2tff(v.w);
        Wyr[i] = v;
    }
    for (int i = start; i < TOPS_N4; i += stride) {
        float4 v = X[i];
        v.x = f2tff(v.x); v.y = f2tff(v.y); v.z = f2tff(v.z); v.w = f2tff(v.w);
        X[i] = v;
    }
}

// ---------- fused 3-gate input GEMM for layer 0 (2-stage cp.async) --------------
__global__ __launch_bounds__(256, 2)
void gemm_ax(const float* __restrict__ A,          // X [M,512]
             const float* __restrict__ Wxl,        // [3,512,512]
             const float* __restrict__ bxl,        // [3,512]
             float* __restrict__ C) {              // [M,1536]
    __shared__ float As[2][BM * AST];
    __shared__ float Bs[2][BKK * BST_KN];

    int tid = threadIdx.x;
    int lane = tid & 31, warp = tid >> 5;
    int wr = warp >> 2, wc = warp & 3;
    int m0 = blockIdx.y * BM, n0 = blockIdx.x * BN;
    int g = n0 >> 9, col0 = n0 & 511;
    const float* Bg = Wxl + (size_t)g * H_DIM * H_DIM;

    const int ra = tid >> 1, ha = tid & 1;
    const int krb = tid >> 4, csb = tid & 15;
    const float* Asrc = A + (size_t)(m0 + ra) * H_DIM + ha * 8;
    const float* Bsrc = Bg + (size_t)krb * H_DIM + col0 + csb * 8;

    float c[4][4][4];
    #pragma unroll
    for (int i = 0; i < 4; i++)
        #pragma unroll
        for (int j = 0; j < 4; j++)
            #pragma unroll
            for (int k = 0; k < 4; k++) c[i][j][k] = 0.f;

    const int NK = H_DIM / BKK;
    {
        unsigned da0 = smem_u32(&As[0][ra * AST + ha * 8]);
        cpa16(da0, Asrc, true); cpa16(da0 + 16, Asrc + 4, true);
        unsigned db0 = smem_u32(&Bs[0][krb * BST_KN + csb * 8]);
        cpa16(db0, Bsrc, true); cpa16(db0 + 16, Bsrc + 4, true);
        cpa_commit();
    }

    for (int it = 0; it < NK; it++) {
        if (it + 1 < NK) {
            int kk = (it + 1) * BKK, buf = (it + 1) & 1;
            unsigned da = smem_u32(&As[buf][ra * AST + ha * 8]);
            cpa16(da, Asrc + kk, true); cpa16(da + 16, Asrc + kk + 4, true);
            unsigned db = smem_u32(&Bs[buf][krb * BST_KN + csb * 8]);
            cpa16(db, Bsrc + (size_t)kk * H_DIM, true);
            cpa16(db + 16, Bsrc + (size_t)kk * H_DIM + 4, true);
        }
        cpa_commit();
        cpa_wait1();
        __syncthreads();

        const float* Ab = As[it & 1];
        const float* Bb = Bs[it & 1];
        int ar = lane >> 2, ak = lane & 3;
        #pragma unroll
        for (int kq = 0; kq < BKK; kq += 8) {
            unsigned af[4][4], bf[4][2];
            #pragma unroll
            for (int mt = 0; mt < 4; mt++) {
                int rb = wr * 64 + mt * 16;
                af[mt][0] = f2tf(Ab[(rb + ar)     * AST + kq + ak]);
                af[mt][1] = f2tf(Ab[(rb + ar + 8) * AST + kq + ak]);
                af[mt][2] = f2tf(Ab[(rb + ar)     * AST + kq + ak + 4]);
                af[mt][3] = f2tf(Ab[(rb + ar + 8) * AST + kq + ak + 4]);
            }
            #pragma unroll
            for (int nt = 0; nt < 4; nt++) {
                int cb = wc * 32 + nt * 8 + (lane >> 2);
                bf[nt][0] = f2tf(Bb[(kq + ak)     * BST_KN + cb]);
                bf[nt][1] = f2tf(Bb[(kq + ak + 4) * BST_KN + cb]);
            }
            #pragma unroll
            for (int mt = 0; mt < 4; mt++)
                #pragma unroll
                for (int nt = 0; nt < 4; nt++)
                    mma8(c[mt][nt], af[mt], bf[nt]);
        }
        __syncthreads();
    }

    #pragma unroll
    for (int mt = 0; mt < 4; mt++) {
        #pragma unroll
        for (int nt = 0; nt < 4; nt++) {
            int r0 = m0 + wr * 64 + mt * 16 + (lane >> 2);
            int cc = n0 + wc * 32 + nt * 8 + (lane & 3) * 2;
            float bv0 = bxl[g * H_DIM + (cc & 511)];
            float bv1 = bxl[g * H_DIM + ((cc + 1) & 511)];
            C[(size_t)r0 * 1536 + cc]           = c[mt][nt][0] + bv0;
            C[(size_t)r0 * 1536 + cc + 1]       = c[mt][nt][1] + bv1;
            C[(size_t)(r0 + 8) * 1536 + cc]     = c[mt][nt][2] + bv0;
            C[(size_t)(r0 + 8) * 1536 + cc + 1] = c[mt][nt][3] + bv1;
        }
    }
}

// ------- logits GEMM, 3-stage cp.async; operands PRE-ROUNDED to tf32 -----------
#define GBUF 2560
__global__ __launch_bounds__(256, 2)
void gemm_bt(const float* __restrict__ A,
             const float* __restrict__ Bm,
             const float* __restrict__ bias,
             float* __restrict__ C, int N) {
    extern __shared__ float sm[];
    float* AsB = sm;
    float* BsB = sm + 3 * GBUF;

    int tid = threadIdx.x;
    int lane = tid & 31, warp = tid >> 5;
    int wr = warp >> 2, wc = warp & 3;
    int m0 = blockIdx.y * BM, n0 = blockIdx.x * BN;

    const int ra = tid >> 1, ha = tid & 1;
    const int gn = n0 + ra;
    const bool bok = (gn < N);
    const float* Asrc = A + (size_t)(m0 + ra) * H_DIM + ha * 8;
    const float* Bsrc = Bm + (size_t)(bok ? gn : 0) * H_DIM + ha * 8;

    float c[4][4][4];
    #pragma unroll
    for (int i = 0; i < 4; i++)
        #pragma unroll
        for (int j = 0; j < 4; j++)
            #pragma unroll
            for (int k = 0; k < 4; k++) c[i][j][k] = 0.f;

    const int NK = H_DIM / BKK;
    #pragma unroll
    for (int s = 0; s < 2; s++) {
        int kk = s * BKK;
        unsigned da = smem_u32(&AsB[s * GBUF + ra * AST + ha * 8]);
        cpa16(da, Asrc + kk, true); cpa16(da + 16, Asrc + kk + 4, true);
        unsigned db = smem_u32(&BsB[s * GBUF + ra * BST_NK + ha * 8]);
        cpa16(db, Bsrc + kk, bok); cpa16(db + 16, Bsrc + kk + 4, bok);
        cpa_commit();
    }

    int buf = 0;
    for (int it = 0; it < NK; it++) {
        cpa_wait1();
        __syncthreads();

        const float* Ab = &AsB[buf * GBUF];
        const float* Bb = &BsB[buf * GBUF];
        int ar = lane >> 2, ak = lane & 3;
        #pragma unroll
        for (int kq = 0; kq < BKK; kq += 8) {
            unsigned af[4][4], bf[4][2];
            #pragma unroll
            for (int mt = 0; mt < 4; mt++) {
                int rb = wr * 64 + mt * 16;
                af[mt][0] = __float_as_uint(Ab[(rb + ar)     * AST + kq + ak]);
                af[mt][1] = __float_as_uint(Ab[(rb + ar + 8) * AST + kq + ak]);
                af[mt][2] = __float_as_uint(Ab[(rb + ar)     * AST + kq + ak + 4]);
                af[mt][3] = __float_as_uint(Ab[(rb + ar + 8) * AST + kq + ak + 4]);
            }
            #pragma unroll
            for (int nt = 0; nt < 4; nt++) {
                int cb = wc * 32 + nt * 8 + (lane >> 2);
                bf[nt][0] = __float_as_uint(Bb[cb * BST_NK + kq + ak]);
                bf[nt][1] = __float_as_uint(Bb[cb * BST_NK + kq + ak + 4]);
            }
            #pragma unroll
            for (int mt = 0; mt < 4; mt++)
                #pragma unroll
                for (int nt = 0; nt < 4; nt++)
                    mma8(c[mt][nt], af[mt], bf[nt]);
        }
        __syncthreads();

        if (it + 2 < NK) {
            int kk = (it + 2) * BKK;
            int nb = (it + 2) % 3;
            unsigned da = smem_u32(&AsB[nb * GBUF + ra * AST + ha * 8]);
            cpa16(da, Asrc + kk, true); cpa16(da + 16, Asrc + kk + 4, true);
            unsigned db = smem_u32(&BsB[nb * GBUF + ra * BST_NK + ha * 8]);
            cpa16(db, Bsrc + kk, bok); cpa16(db + 16, Bsrc + kk + 4, bok);
        }
        cpa_commit();
        buf = (buf + 1) % 3;
    }

    #pragma unroll
    for (int mt = 0; mt < 4; mt++) {
        #pragma unroll
        for (int nt = 0; nt < 4; nt++) {
            int r0 = m0 + wr * 64 + mt * 16 + (lane >> 2);
            int cc = n0 + wc * 32 + nt * 8 + (lane & 3) * 2;
            if (cc < N) {
                float bv = bias[cc];
                C[(size_t)r0 * N + cc]       = c[mt][nt][0] + bv;
                C[(size_t)(r0 + 8) * N + cc] = c[mt][nt][2] + bv;
            }
            if (cc + 1 < N) {
                float bv = bias[cc + 1];
                C[(size_t)r0 * N + cc + 1]       = c[mt][nt][1] + bv;
                C[(size_t)(r0 + 8) * N + cc + 1] = c[mt][nt][3] + bv;
            }
        }
    }
}

// ========== fused two-layer pipelined GRU recurrence — TENSOR-CORE phases =======
// CTA = (bg 0..1, og 0..63): 8 outputs x 16 batches, BOTH layers.
// vt = 0..128: layer-0 step vt (vt<128), layer-1 step vt-1 (vt>0).
// Phase dots via mma.m16n8k8 tf32: A = staged h (tf32-rounded, 16 batches x k),
// B = weights [o][k] (tf32-rounded once). Carried state h stays FULL fp32 in
// g_h0/g_h1 (hold read from global, never from the rounded smem copy).
#define HST 1028          // hS / W1 row stride (floats)
#define W0ST 516          // W0 row stride
__global__ __launch_bounds__(256)
void recur_fused(const float* __restrict__ A,     // layer-0 ax [S,32,1536]
                 const float* __restrict__ U,     // [2,3,512,512]
                 const float* __restrict__ Wx,    // [2,3,512,512]
                 const float* __restrict__ bx,    // [2,3,512]
                 const float* __restrict__ h0in,  // [2,32,512]
                 float* __restrict__ Y,           // tops [S,32,512]
                 float* __restrict__ hfin) {      // [2,32,512]
    extern __shared__ float smem[];
    float* W0    = smem;                          // 24 x 516  (r,z,c x 8 o) tf32
    float* W1    = W0 + 24 * W0ST;                // 24 x 1028 (concat Wx1|U1) tf32
    float* hS    = W1 + 24 * HST;                 // 16 b x 1028 (tf32 operands)
    float* redS  = hS + 16 * HST;                 // 32x34 (p1) / 8x136 (p2)
    float* zS    = redS + 32 * 34;                // 16 x 17
    float* holdS = zS + 16 * 17;                  // 16 x 17

    const int tid = threadIdx.x, lane = tid & 31, w = tid >> 5;
    const int og = blockIdx.x & 63, bg = blockIdx.x >> 6;
    const int o0 = og * 8;

    // fragment coords (shared by all mma phases)
    const int ar = lane >> 2, ak = lane & 3;      // A/B row, k-offset
    const int cc2 = (lane & 3) * 2;               // C col base
    // finalize roles
    const int frow = tid >> 4, fb = tid & 15;
    const int fo = o0 + (frow & 7);
    const int fbglob = bg * 16 + fb;

    // ---- stage weights once (tf32-rounded) ----
    for (int idx = tid; idx < 12288; idx += 256) {
        int g = idx >> 12, r = idx & 4095, k = r >> 3, ol = r & 7;
        W0[(g * 8 + ol) * W0ST + k] =
            f2tff(U[(size_t)g * 262144 + (size_t)k * 512 + o0 + ol]);
    }
    for (int idx = tid; idx < 24576; idx += 256) {
        int g = idx >> 13, r = idx & 8191, k = r >> 3, ol = r & 7;
        float v;
        if (k < 512) v = Wx[(size_t)(3 + g) * 262144 + (size_t)k * 512 + o0 + ol];
        else         v = U[(size_t)(3 + g) * 262144 + (size_t)(k - 512) * 512 + o0 + ol];
        W1[(g * 8 + ol) * HST + k] = f2tff(v);
    }

    float av1b = __ldg(&bx[(size_t)(3 + (frow >> 3)) * 512 + fo]);
    float av2b = (tid < 128) ? __ldg(&bx[(size_t)5 * 512 + o0 + (tid >> 4)]) : 0.f;

    // ---- seed h states (og==0 CTA per bg) ----
    if (og == 0) {
        for (int i = tid; i < 2048; i += 256) {
            int b = i >> 7, f = i & 127;
            float4 v0 = *(const float4*)(h0in + (size_t)(bg * 16 + b) * 512 + f * 4);
            float4 v1 = *(const float4*)(h0in + 16384 + (size_t)(bg * 16 + b) * 512 + f * 4);
            __stcg((float4*)(g_h0 + (size_t)(bg * 16 + b) * 512 + f * 4), v0);
            __stcg((float4*)(g_h1 + (size_t)(bg * 16 + b) * 512 + f * 4), v1);
        }
    }
    bg_barrier(bg);

    for (int vt = 0; vt <= S_LEN; ++vt) {
        const bool l0 = (vt < S_LEN);
        const bool l1 = (vt > 0);
        const int t1 = vt - 1;

        // prefetch A operands + FULL-precision holds for finalize roles
        float av1a = 0.f, av2a = 0.f, hold0pre = 0.f, hold1pre = 0.f;
        if (l0) {
            av1a = __ldg(&A[((size_t)vt * 32 + fbglob) * 1536 + (frow >> 3) * 512 + fo]);
            if (tid < 128)
                av2a = __ldg(&A[((size_t)vt * 32 + fbglob) * 1536 + 1024 + o0 + (tid >> 4)]);
        }
        if (frow < 8) {
            hold0pre = __ldg(&g_h0[(size_t)fbglob * 512 + fo]);
            hold1pre = __ldg(&g_h1[(size_t)fbglob * 512 + fo]);
        }

        // ---- stage h0prev and h1prev (tf32-rounded mma operands) ----
        for (int i = tid; i < 2048; i += 256) {
            int b = i >> 7, f = i & 127;
            float4 v = __ldcg((const float4*)(g_h0 + (size_t)(bg * 16 + b) * 512 + f * 4));
            v.x = f2tff(v.x); v.y = f2tff(v.y); v.z = f2tff(v.z); v.w = f2tff(v.w);
            *(float4*)&hS[b * HST + f * 4] = v;
        }
        if (l1) {
            for (int i = tid; i < 2048; i += 256) {
                int b = i >> 7, f = i & 127;
                float4 v = __ldcg((const float4*)(g_h1 + (size_t)(bg * 16 + b) * 512 + f * 4));
                v.x = f2tff(v.x); v.y = f2tff(v.y); v.z = f2tff(v.z); v.w = f2tff(v.w);
                *(float4*)&hS[b * HST + 512 + f * 4] = v;
            }
        }
        __syncthreads();

        // ---- phase 1 compute (mma): warps 0-3 -> L0 (K=512), warps 4-7 -> L1 (K=1024)
        {
            float cr[4] = {0.f, 0.f, 0.f, 0.f};
            if (w < 4) {
                if (l0) {
                    int nt = w & 1, kh = w >> 1;
                    const float* Brow = W0 + (size_t)nt * 8 * W0ST;
                    #pragma unroll 4
                    for (int kt = 0; kt < 32; kt++) {
                        int kb = kh * 256 + kt * 8;
                        unsigned af[4], bf[2];
                        af[0] = __float_as_uint(hS[ar * HST + kb + ak]);
                        af[1] = __float_as_uint(hS[(ar + 8) * HST + kb + ak]);
                        af[2] = __float_as_uint(hS[ar * HST + kb + ak + 4]);
                        af[3] = __float_as_uint(hS[(ar + 8) * HST + kb + ak + 4]);
                        bf[0] = __float_as_uint(Brow[ar * W0ST + kb + ak]);
                        bf[1] = __float_as_uint(Brow[ar * W0ST + kb + ak + 4]);
                        mma8(cr, af, bf);
                    }
                    int colb = nt * 8, kh2 = kh;
                    redS[(colb + cc2)     * 34 + ar * 2 + kh2]       = cr[0];
                    redS[(colb + cc2 + 1) * 34 + ar * 2 + kh2]       = cr[1];
                    redS[(colb + cc2)     * 34 + (ar + 8) * 2 + kh2] = cr[2];
                    redS[(colb + cc2 + 1) * 34 + (ar + 8) * 2 + kh2] = cr[3];
                }
            } else {
                if (l1) {
                    int ww = w - 4, nt = ww & 1, kh = ww >> 1;
                    const float* Brow = W1 + (size_t)nt * 8 * HST;
                    #pragma unroll 4
                    for (int kt = 0; kt < 64; kt++) {
                        int kb = kh * 512 + kt * 8;
                        unsigned af[4], bf[2];
                        af[0] = __float_as_uint(hS[ar * HST + kb + ak]);
                        af[1] = __float_as_uint(hS[(ar + 8) * HST + kb + ak]);
                        af[2] = __float_as_uint(hS[ar * HST + kb + ak + 4]);
                        af[3] = __float_as_uint(hS[(ar + 8) * HST + kb + ak + 4]);
                        bf[0] = __float_as_uint(Brow[ar * HST + kb + ak]);
                        bf[1] = __float_as_uint(Brow[ar * HST + kb + ak + 4]);
                        mma8(cr, af, bf);
                    }
                    int colb = 16 + nt * 8, kh2 = kh;
                    redS[(colb + cc2)     * 34 + ar * 2 + kh2]       = cr[0];
                    redS[(colb + cc2 + 1) * 34 + ar * 2 + kh2]       = cr[1];
                    redS[(colb + cc2)     * 34 + (ar + 8) * 2 + kh2] = cr[2];
                    redS[(colb + cc2 + 1) * 34 + (ar + 8) * 2 + kh2] = cr[3];
                }
            }
        }
        __syncthreads();

        // ---- phase 1 finalize (hold from FULL-precision prefetch) ----
        if (l0) {
            float s = redS[frow * 34 + fb * 2] + redS[frow * 34 + fb * 2 + 1] + av1a;
            float sg = 1.f / (1.f + __expf(-s));
            if (frow < 8) {
                holdS[frow * 17 + fb] = hold0pre;
                __stcg(&g_rh0[(size_t)fbglob * 512 + fo], sg * hold0pre);
            } else {
                zS[(frow - 8) * 17 + fb] = sg;
            }
        }
        if (l1) {
            int row1 = 16 + frow;
            float s = redS[row1 * 34 + fb * 2] + redS[row1 * 34 + fb * 2 + 1] + av1b;
            float sg = 1.f / (1.f + __expf(-s));
            if (frow < 8) {
                holdS[(8 + frow) * 17 + fb] = hold1pre;
                __stcg(&g_rh1[(size_t)fbglob * 512 + fo], sg * hold1pre);
            } else {
                zS[(8 + frow - 8) * 17 + fb] = sg;
            }
        }
        bg_barrier(bg);

        // ---- stage rh0 into second slot (rounded) ----
        if (l0) {
            for (int i = tid; i < 2048; i += 256) {
                int b = i >> 7, f = i & 127;
                float4 v = __ldcg((const float4*)(g_rh0 + (size_t)(bg * 16 + b) * 512 + f * 4));
                v.x = f2tff(v.x); v.y = f2tff(v.y); v.z = f2tff(v.z); v.w = f2tff(v.w);
                *(float4*)&hS[b * HST + 512 + f * 4] = v;
            }
        }
        __syncthreads();

        // ---- phase 2 L0 compute (mma): all 8 warps, 8-way k-split of K=512 ----
        if (l0) {
            float cr[4] = {0.f, 0.f, 0.f, 0.f};
            const float* Brow = W0 + (size_t)16 * W0ST;
            #pragma unroll 4
            for (int kt = 0; kt < 8; kt++) {
                int kb = 512 + w * 64 + kt * 8;      // rh0 lives at +512
                int kbw = w * 64 + kt * 8;           // weight k-index
                unsigned af[4], bf[2];
                af[0] = __float_as_uint(hS[ar * HST + kb + ak]);
                af[1] = __float_as_uint(hS[(ar + 8) * HST + kb + ak]);
                af[2] = __float_as_uint(hS[ar * HST + kb + ak + 4]);
                af[3] = __float_as_uint(hS[(ar + 8) * HST + kb + ak + 4]);
                bf[0] = __float_as_uint(Brow[ar * W0ST + kbw + ak]);
                bf[1] = __float_as_uint(Brow[ar * W0ST + kbw + ak + 4]);
                mma8(cr, af, bf);
            }
            redS[(cc2)     * 136 + ar * 8 + w]       = cr[0];
            redS[(cc2 + 1) * 136 + ar * 8 + w]       = cr[1];
            redS[(cc2)     * 136 + (ar + 8) * 8 + w] = cr[2];
            redS[(cc2 + 1) * 136 + (ar + 8) * 8 + w] = cr[3];
        }
        __syncthreads();

        // ---- phase 2 L0 finalize + restage rh1 ----
        if (l0 && tid < 128) {
            int row = tid >> 4;
            float4 p  = *(const float4*)&redS[row * 136 + fb * 8];
            float4 p2 = *(const float4*)&redS[row * 136 + fb * 8 + 4];
            float tot = ((p.x + p.y) + (p.z + p.w)) + ((p2.x + p2.y) + (p2.z + p2.w));
            float hh = tanhf(tot + av2a);
            float z = zS[row * 17 + fb];
            float hold = holdS[row * 17 + fb];
            float hn = fmaf(z, hh - hold, hold);
            __stcg(&g_h0[(size_t)fbglob * 512 + o0 + row], hn);
        }
        if (l1) {
            for (int i = tid; i < 2048; i += 256) {
                int b = i >> 7, f = i & 127;
                float4 v = __ldcg((const float4*)(g_rh1 + (size_t)(bg * 16 + b) * 512 + f * 4));
                v.x = f2tff(v.x); v.y = f2tff(v.y); v.z = f2tff(v.z); v.w = f2tff(v.w);
                *(float4*)&hS[b * HST + 512 + f * 4] = v;
            }
        }
        __syncthreads();

        // ---- phase 2 L1 compute (mma): concat [y0 | rh1], 8-way split of K=1024
        if (l1) {
            float cr[4] = {0.f, 0.f, 0.f, 0.f};
            const float* Brow = W1 + (size_t)16 * HST;
            #pragma unroll 4
            for (int kt = 0; kt < 16; kt++) {
                int kb = w * 128 + kt * 8;
                unsigned af[4], bf[2];
                af[0] = __float_as_uint(hS[ar * HST + kb + ak]);
                af[1] = __float_as_uint(hS[(ar + 8) * HST + kb + ak]);
                af[2] = __float_as_uint(hS[ar * HST + kb + ak + 4]);
                af[3] = __float_as_uint(hS[(ar + 8) * HST + kb + ak + 4]);
                bf[0] = __float_as_uint(Brow[ar * HST + kb + ak]);
                bf[1] = __float_as_uint(Brow[ar * HST + kb + ak + 4]);
                mma8(cr, af, bf);
            }
            redS[(cc2)     * 136 + ar * 8 + w]       = cr[0];
            redS[(cc2 + 1) * 136 + ar * 8 + w]       = cr[1];
            redS[(cc2)     * 136 + (ar + 8) * 8 + w] = cr[2];
            redS[(cc2 + 1) * 136 + (ar + 8) * 8 + w] = cr[3];
        }
        __syncthreads();

        // ---- phase 2 L1 finalize ----
        if (l1 && tid < 128) {
            int row = tid >> 4;
            float4 p  = *(const float4*)&redS[row * 136 + fb * 8];
            float4 p2 = *(const float4*)&redS[row * 136 + fb * 8 + 4];
            float tot = ((p.x + p.y) + (p.z + p.w)) + ((p2.x + p2.y) + (p2.z + p2.w));
            float hh = tanhf(tot + av2b);
            float z = zS[(8 + row) * 17 + fb];
            float hold = holdS[(8 + row) * 17 + fb];
            float hn = fmaf(z, hh - hold, hold);
            __stcg(&g_h1[(size_t)fbglob * 512 + o0 + row], hn);
            __stcg(&Y[((size_t)t1 * 32 + fbglob) * 512 + o0 + row], hn);
        }
        bg_barrier(bg);
    }

    // ---- final hidden states ----
    if (og == 0) {
        for (int i = tid; i < 2048; i += 256) {
            int b = i >> 7, f = i & 127;
            float4 v0 = __ldcg((const float4*)(g_h0 + (size_t)(bg * 16 + b) * 512 + f * 4));
            float4 v1 = __ldcg((const float4*)(g_h1 + (size_t)(bg * 16 + b) * 512 + f * 4));
            *(float4*)(hfin + (size_t)(bg * 16 + b) * 512 + f * 4) = v0;
            *(float4*)(hfin + 16384 + (size_t)(bg * 16 + b) * 512 + f * 4) = v1;
        }
    }
}

// ---------------- launch ----------------
extern "C" void kernel_launch(void* const* d_in, const int* in_sizes, int n_in,
                              void* d_out, int out_size) {
    const void*  tokens = d_in[0];
    const float* h0  = (const float*)d_in[1];
    const float* emb = (const float*)d_in[2];
    const float* Wx  = (const float*)d_in[3];
    const float* bx  = (const float*)d_in[4];
    const float* U   = (const float*)d_in[5];
    const float* Wy  = (const float*)d_in[6];
    const float* by  = (const float*)d_in[7];

    float* logits = (float*)d_out;                              // [S,B,V]
    float* hfin   = logits + (size_t)S_LEN * B_SZ * V_SZ;       // [L,B,H]

    float *dX, *dA;
    cudaGetSymbolAddress((void**)&dX, g_X);
    cudaGetSymbolAddress((void**)&dA, g_A);

    const int M = S_LEN * B_SZ;
    const int RSMEM = (24 * W0ST + 24 * HST + 16 * HST + 32 * 34 + 2 * 16 * 17) * 4;
    cudaFuncSetAttribute(recur_fused, cudaFuncAttributeMaxDynamicSharedMemorySize, RSMEM);
    const int GSMEM = 6 * GBUF * 4;
    cudaFuncSetAttribute(gemm_bt, cudaFuncAttributeMaxDynamicSharedMemorySize, GSMEM);

    dim3 blk(256);

    detect_kernel<<<1, 32>>>((const int*)tokens);
    embed_kernel<<<M, 128>>>(tokens, emb, dX);

    // A0 = X @ Wx[0] + bx[0] (layer 0 only)
    gemm_ax<<<dim3(12, M / 128), blk>>>(dX, Wx, bx, dA);

    // fused two-layer pipelined recurrence -> tops into dX, finals into hfin
    recur_fused<<<128, 256, RSMEM>>>(dA, U, Wx, bx, h0, dX, hfin);

    // pre-round logits operands to tf32 (tops in place; Wy -> g_A)
    round_tf32_kernel<<<1184, 256>>>((float4*)dX, (const float4*)Wy, (float4*)dA);

    // logits = round(tops) @ round(Wy)^T + by
    gemm_bt<<<dim3((V_SZ + 127) / 128, M / 128), blk, GSMEM>>>(dX, dA, by, logits, V_SZ);
}